// round 9
// baseline (speedup 1.0000x reference)
#include <cuda_runtime.h>
#include <math.h>

#define NG 256
#define IMG_H 512
#define IMG_W 512
#define RBLK 128   // 1024 blocks; each covers a 128x2 pixel strip

// 1/(2*ln(2)) : folds exp(-0.5*mahal) -> single ex2; cancels inside tau.
#define S_CONST 0.7213475204444817f

// Sorted, preprocessed gaussian table (10 scalars per gaussian):
//   gA = (q0, q1, q2, s0)     q = mu * sinv',  s = sinv' = S_CONST * exp(-2*ls)
//   gB = (s1, s2, kcol, c0)   kcol = log2(sigmoid(rop)) - sum(q*mu)
//   gC = (c1, c2, -, -)       c = sigmoid(colors)
__device__ float4 g_A[NG];
__device__ float4 g_B[NG];
__device__ float4 g_C[NG];

typedef unsigned long long u64;

__device__ __forceinline__ u64 pk(float lo, float hi) {
    u64 r; asm("mov.b64 %0, {%1, %2};" : "=l"(r) : "f"(lo), "f"(hi)); return r;
}
__device__ __forceinline__ void upk(u64 v, float& lo, float& hi) {
    asm("mov.b64 {%0, %1}, %2;" : "=f"(lo), "=f"(hi) : "l"(v));
}
__device__ __forceinline__ u64 dup2(float x) { return pk(x, x); }
__device__ __forceinline__ u64 f2mul(u64 a, u64 b) {
    u64 r; asm("mul.rn.f32x2 %0, %1, %2;" : "=l"(r) : "l"(a), "l"(b)); return r;
}
__device__ __forceinline__ u64 f2fma(u64 a, u64 b, u64 c) {
    u64 r; asm("fma.rn.f32x2 %0, %1, %2, %3;" : "=l"(r) : "l"(a), "l"(b), "l"(c)); return r;
}
__device__ __forceinline__ float rcpa(float x) {
    float r; asm("rcp.approx.f32 %0, %1;" : "=f"(r) : "f"(x)); return r;
}
__device__ __forceinline__ float ex2a(float x) {
    float r; asm("ex2.approx.f32 %0, %1;" : "=f"(r) : "f"(x)); return r;
}

__global__ void prep_kernel(const float* __restrict__ pos,
                            const float* __restrict__ ls,
                            const float* __restrict__ rop,
                            const float* __restrict__ col) {
    __shared__ float zs[NG];
    int i = threadIdx.x;

    float m0 = pos[3 * i + 0];
    float m1 = pos[3 * i + 1];
    float m2 = pos[3 * i + 2];
    zs[i] = m2;
    __syncthreads();

    // Stable rank (matches stable argsort): O(N^2), trivial at N=256.
    int rank = 0;
    #pragma unroll 8
    for (int j = 0; j < NG; j++) {
        float zj = zs[j];
        rank += (zj < m2) || (zj == m2 && j < i);
    }

    // sinv' = S_CONST * exp(-2*ls)
    float s0 = S_CONST * expf(-2.0f * ls[3 * i + 0]);
    float s1 = S_CONST * expf(-2.0f * ls[3 * i + 1]);
    float s2 = S_CONST * expf(-2.0f * ls[3 * i + 2]);
    float q0 = m0 * s0, q1 = m1 * s1, q2 = m2 * s2;
    float kp = q0 * m0 + q1 * m1 + q2 * m2;

    float a0 = 1.0f / (1.0f + expf(-rop[i]));
    float kcol = log2f(a0) - kp;           // alpha = 2^(num^2/den - kp + log2 a0)

    float c0 = 1.0f / (1.0f + expf(-col[3 * i + 0]));
    float c1 = 1.0f / (1.0f + expf(-col[3 * i + 1]));
    float c2 = 1.0f / (1.0f + expf(-col[3 * i + 2]));

    g_A[rank] = make_float4(q0, q1, q2, s0);
    g_B[rank] = make_float4(s1, s2, kcol, c0);
    g_C[rank] = make_float4(c1, c2, 0.0f, 0.0f);
}

// Per-gaussian compositing step for 2 packed pixels. L points at this
// gaussian's 5 pre-duplicated f32x2 pairs in shared memory.
struct Ray2 { u64 d0, d1, dd0, dd1, ntp; };

__device__ __forceinline__ void comp_step(const ulonglong2* __restrict__ L,
                                          const Ray2& r,
                                          u64& T, u64& i0, u64& i1, u64& i2) {
    const u64 HUGE2 = 0x7E9676997E967699ull;   // dup2(1e38f)
    const u64 NEG1  = 0xBF800000BF800000ull;   // dup2(-1.0f)

    ulonglong2 L0 = L[0];
    ulonglong2 L1 = L[1];
    ulonglong2 L2 = L[2];
    ulonglong2 L3 = L[3];
    ulonglong2 L4 = L[4];

    // num = q0*dx + q1*dy + q2 ; den = s0*dx^2 + s1*dy^2 + s2
    u64 num = f2fma(r.d0, L0.x, f2fma(r.d1, L0.y, L1.x));
    u64 den = f2fma(r.dd0, L1.y, f2fma(r.dd1, L2.x, L2.y));

    // margin m > 0 <=> tau > 0.1; gate = m*1e38 (>=0/+inf valid, huge-neg invalid)
    u64 m    = f2fma(den, r.ntp, num);
    u64 gate = f2mul(m, HUGE2);

    float de0, de1; upk(den, de0, de1);
    u64 rp = pk(rcpa(de0), rcpa(de1));

    // e = num^2/den + (log2(a0) - k)  (always <= log2 a0 < 0 by Cauchy-Schwarz)
    u64 nr = f2mul(num, rp);
    u64 e  = f2fma(num, nr, L3.x);

    float e0, e1, g0, g1;
    upk(e, e0, e1);
    upk(gate, g0, g1);
    u64 ex = pk(ex2a(fminf(e0, g0)), ex2a(fminf(e1, g1)));  // alpha (a0 folded in)

    u64 w = f2mul(T, ex);
    i0 = f2fma(w, L3.y, i0);
    i1 = f2fma(w, L4.x, i1);
    i2 = f2fma(w, L4.y, i2);
    T  = f2fma(w, NEG1, T);               // T *= (1 - alpha)
}

// 2 vertically-adjacent pixels per thread, packed f32x2 math throughout.
// Per-block conservative culling compacts the gaussian list before the
// main loop; survivors keep their front-to-back order.
__global__ void __launch_bounds__(RBLK) render_kernel(float* __restrict__ out) {
    __shared__ ulonglong2 sd[(NG + 1) * 5];  // +1 null slot for padding
    __shared__ unsigned short sidx[NG + 4];
    __shared__ int scnt[8];
    __shared__ int s_n4;

    int t = threadIdx.x;
    int bid = blockIdx.x;

    // ---- tile extent (u in [u0, u0+127], v in {v0, v0+1}) ----
    int u0 = (bid * RBLK) & (IMG_W - 1);
    int v0 = (bid >> 2) * 2;
    float dxlo = ((float)u0 + 0.5f - 256.0f) * (1.0f / 500.0f);
    float dxhi = ((float)(u0 + RBLK - 1) + 0.5f - 256.0f) * (1.0f / 500.0f);
    float dyA  = ((float)v0 + 0.5f - 256.0f) * (1.0f / 500.0f);
    float dyB  = ((float)v0 + 1.5f - 256.0f) * (1.0f / 500.0f);

    float mindx2 = (dxlo * dxhi <= 0.0f) ? 0.0f : fminf(dxlo * dxlo, dxhi * dxhi);
    float mindy2 = (dyA * dyB  <= 0.0f) ? 0.0f : fminf(dyA * dyA, dyB * dyB);
    float maxdx2 = fmaxf(dxlo * dxlo, dxhi * dxhi);
    float maxdy2 = fmaxf(dyA * dyA, dyB * dyB);
    // lower bound on per-pixel 0.1/|dir| (rsqrt approx covered by the -1e-5 slack)
    float thr_min = 0.1f * rsqrtf(maxdx2 + maxdy2 + 1.0f);

    // ---- build duplicated shared table + cull flags (2 gaussians/thread) ----
    unsigned km[2];
    bool     kf[2];
    #pragma unroll
    for (int j = 0; j < 2; j++) {
        int gi = j * RBLK + t;
        float4 A = g_A[gi];
        float4 B = g_B[gi];
        float4 C = g_C[gi];
        sd[5 * gi + 0] = make_ulonglong2(dup2(A.x), dup2(A.y));  // q0 q1
        sd[5 * gi + 1] = make_ulonglong2(dup2(A.z), dup2(A.w));  // q2 s0
        sd[5 * gi + 2] = make_ulonglong2(dup2(B.x), dup2(B.y));  // s1 s2
        sd[5 * gi + 3] = make_ulonglong2(dup2(B.z), dup2(B.w));  // kcol c0
        sd[5 * gi + 4] = make_ulonglong2(dup2(C.x), dup2(C.y));  // c1 c2

        // interval bounds over the tile
        float numhi = A.z + fmaxf(A.x * dxlo, A.x * dxhi) + fmaxf(A.y * dyA, A.y * dyB);
        float numlo = A.z + fminf(A.x * dxlo, A.x * dxhi) + fminf(A.y * dyA, A.y * dyB);
        float den_min = A.w * mindx2 + B.x * mindy2 + B.y;   // > 0 (s2 > 0)
        float num2max = fmaxf(numhi * numhi, numlo * numlo);

        float m_ub = numhi - thr_min * den_min;              // >= margin at every pixel
        float e_ub = num2max / den_min + B.z;                // >= exponent at every pixel
        bool keep = (m_ub > -1e-5f) && (e_ub > -26.0f);

        km[j] = __ballot_sync(0xffffffffu, keep);
        kf[j] = keep;
        if ((t & 31) == 0) scnt[j * 4 + (t >> 5)] = __popc(km[j]);
    }
    if (t == 0) {   // null gaussian (slot NG): alpha == 0 always, no NaN path
        sd[NG * 5 + 0] = make_ulonglong2(0ull, 0ull);               // q0 q1 = 0
        sd[NG * 5 + 1] = make_ulonglong2(0ull, 0ull);               // q2 s0 = 0
        sd[NG * 5 + 2] = make_ulonglong2(0ull, dup2(1.0f));         // s1=0 s2=1
        sd[NG * 5 + 3] = make_ulonglong2(dup2(-100.0f), 0ull);      // kcol c0
        sd[NG * 5 + 4] = make_ulonglong2(0ull, 0ull);               // c1 c2
    }
    __syncthreads();

    // ---- ordered compaction into sidx ----
    int lane = t & 31;
    #pragma unroll
    for (int j = 0; j < 2; j++) {
        if (kf[j]) {
            int seg = j * 4 + (t >> 5);
            int off = 0;
            #pragma unroll
            for (int s = 0; s < 8; s++) off += (s < seg) ? scnt[s] : 0;
            int rank = __popc(km[j] & ((1u << lane) - 1u));
            sidx[off + rank] = (unsigned short)(j * RBLK + t);
        }
    }
    if (t == 0) {
        int n = scnt[0] + scnt[1] + scnt[2] + scnt[3]
              + scnt[4] + scnt[5] + scnt[6] + scnt[7];
        int n4 = (n + 3) & ~3;
        for (int p = n; p < n4; p++) sidx[p] = (unsigned short)NG;
        s_n4 = n4;
    }
    __syncthreads();
    int n4 = s_n4;

    // ---- per-thread ray setup (2 pixels: rows v0, v0+1 at column u0+t) ----
    int u = u0 + t;
    float dx = ((float)u + 0.5f - 256.0f) * (1.0f / 500.0f);

    Ray2 r;
    r.d0  = dup2(dx);
    r.d1  = pk(dyA, dyB);
    r.dd0 = f2mul(r.d0, r.d0);
    r.dd1 = f2mul(r.d1, r.d1);
    // validity: tau_unit = |dir| * num/den > 0.1  <=>  num - (0.1/|dir|)*den > 0
    r.ntp = pk(-0.1f * rsqrtf(fmaf(dx, dx, fmaf(dyA, dyA, 1.0f))),
               -0.1f * rsqrtf(fmaf(dx, dx, fmaf(dyB, dyB, 1.0f))));

    u64 T  = pk(1.0f, 1.0f);
    u64 i0 = 0ull, i1 = 0ull, i2 = 0ull;

    // ---- main loop over surviving gaussians (indices fetched 4-at-a-time) ----
    for (int g = 0; g < n4; g += 4) {
        ushort4 idx4 = *reinterpret_cast<const ushort4*>(sidx + g);  // 8B aligned
        comp_step(sd + 5 * (int)idx4.x, r, T, i0, i1, i2);
        comp_step(sd + 5 * (int)idx4.y, r, T, i0, i1, i2);
        comp_step(sd + 5 * (int)idx4.z, r, T, i0, i1, i2);
        comp_step(sd + 5 * (int)idx4.w, r, T, i0, i1, i2);

        float Tl, Th; upk(T, Tl, Th);
        if (__all_sync(0xffffffffu, fmaxf(Tl, Th) < 1e-5f)) break;
    }

    int p0 = v0 * IMG_W + u;
    int p1 = p0 + IMG_W;
    float a, b, Tl, Th;
    upk(T, Tl, Th);
    upk(i0, a, b); out[3 * p0 + 0] = a + Tl; out[3 * p1 + 0] = b + Th;
    upk(i1, a, b); out[3 * p0 + 1] = a + Tl; out[3 * p1 + 1] = b + Th;
    upk(i2, a, b); out[3 * p0 + 2] = a + Tl; out[3 * p1 + 2] = b + Th;
}

extern "C" void kernel_launch(void* const* d_in, const int* in_sizes, int n_in,
                              void* d_out, int out_size) {
    const float* positions   = (const float*)d_in[0];
    const float* log_scales  = (const float*)d_in[1];
    const float* raw_opacity = (const float*)d_in[2];
    const float* colors      = (const float*)d_in[3];
    float* out = (float*)d_out;

    prep_kernel<<<1, NG>>>(positions, log_scales, raw_opacity, colors);
    render_kernel<<<(IMG_H * IMG_W) / (2 * RBLK), RBLK>>>(out);
}